// round 8
// baseline (speedup 1.0000x reference)
#include <cuda_runtime.h>

#define BMAX 16384
#define L 16
#define D 8
#define U 128
#define P 8
#define ROW (L*D + 1)
#define NBMAX (BMAX/8)

// ---- composed-weight + softmax scratch (static device arrays; no allocs) ----
__device__ float g_WqT[D*U],  g_bq[U];   // sq_w composed with le_w (transposed [d][u])
__device__ float g_WrT[D*U],  g_br[U];   // sr_w composed
__device__ float g_WaqT[D*U], g_caq[U];  // aq_w composed (caq = aq_w@le_b)
__device__ float g_WarT[D*U], g_car[U];  // ar_w composed
__device__ float g_elog[(size_t)BMAX*L];    // exp(logit)
__device__ float g_part[(size_t)NBMAX*L];   // per-block partial sums of exp
__device__ float g_invden[L];
__device__ unsigned int g_ticket;           // last-block-done counter (reset by last block)

__device__ __forceinline__ float fast_tanh(float x) {
    float y;
    asm("tanh.approx.f32 %0, %1;" : "=f"(y) : "f"(x));
    return y;
}

// Multi-value butterfly: v[0] on lane r ends with 32-lane sum of index rev3(r&7).
__device__ __forceinline__ void red8(float v[8], int lane) {
#pragma unroll
    for (int m = 1; m <= 4; m <<= 1) {
        int n = (m == 1) ? 8 : (m == 2) ? 4 : 2;
        int h = n >> 1;
        bool up = (lane & m) != 0;
#pragma unroll
        for (int i = 0; i < 4; i++) {
            if (i < h) {
                float send = up ? v[i] : v[i + h];
                float recv = __shfl_xor_sync(0xffffffffu, send, m);
                v[i] = (up ? v[i + h] : v[i]) + recv;
            }
        }
    }
    v[0] += __shfl_xor_sync(0xffffffffu, v[0], 8);
    v[0] += __shfl_xor_sync(0xffffffffu, v[0], 16);
}

__device__ __forceinline__ int rev3(int r) {
    return ((r & 1) << 2) | (r & 2) | ((r & 4) >> 2);
}

// dot of (a0|a1) with 8 scalar weights
__device__ __forceinline__ float dot8v(float4 a0, float4 a1, const float* w, float init) {
    float q = init;
    q = fmaf(a0.x, w[0], q); q = fmaf(a0.y, w[1], q);
    q = fmaf(a0.z, w[2], q); q = fmaf(a0.w, w[3], q);
    q = fmaf(a1.x, w[4], q); q = fmaf(a1.y, w[5], q);
    q = fmaf(a1.z, w[6], q); q = fmaf(a1.w, w[7], q);
    return q;
}

// ---------------------------------------------------------------------------
// Kernel 0: fold le_w/le_b through the four 128x128 linears. Split-K halves.
// ---------------------------------------------------------------------------
__global__ void k_compose(const float* __restrict__ le_w, const float* __restrict__ le_b,
                          const float* __restrict__ sq_w, const float* __restrict__ sq_b,
                          const float* __restrict__ sr_w, const float* __restrict__ sr_b,
                          const float* __restrict__ aq_w,
                          const float* __restrict__ ar_w) {
    __shared__ float sle[U*D], sleb[U];
    __shared__ float spart[U][D + 1];
    int tid = threadIdx.x;
    int u = tid & 127, half = tid >> 7;
    if (half == 0) {
#pragma unroll
        for (int d = 0; d < D; d++) sle[u*D + d] = le_w[u*D + d];
        sleb[u] = le_b[u];
    }
    __syncthreads();

    int m = blockIdx.x;
    const float* W = (m == 0) ? sq_w : (m == 1) ? sr_w : (m == 2) ? aq_w : ar_w;

    float acc[D];
#pragma unroll
    for (int d = 0; d < D; d++) acc[d] = 0.0f;
    float ab = 0.0f;
    int k0 = half * (U/2);
    for (int k = k0; k < k0 + U/2; k++) {
        float w = W[u*U + k];
        ab = fmaf(w, sleb[k], ab);
#pragma unroll
        for (int d = 0; d < D; d++) acc[d] = fmaf(w, sle[k*D + d], acc[d]);
    }
    if (half == 1) {
#pragma unroll
        for (int d = 0; d < D; d++) spart[u][d] = acc[d];
        spart[u][D] = ab;
    }
    __syncthreads();
    if (half == 0) {
#pragma unroll
        for (int d = 0; d < D; d++) acc[d] += spart[u][d];
        ab += spart[u][D];
        float* WT = (m == 0) ? g_WqT : (m == 1) ? g_WrT : (m == 2) ? g_WaqT : g_WarT;
#pragma unroll
        for (int d = 0; d < D; d++) WT[d*U + u] = acc[d];
        if      (m == 0) g_bq[u]  = ab + sq_b[u];
        else if (m == 1) g_br[u]  = ab + sr_b[u];
        else if (m == 2) g_caq[u] = ab;
        else             g_car[u] = ab;
    }
}

// ---------------------------------------------------------------------------
// Kernel 1: attention logits -> exp(logit) + per-block partials + fused
// last-block denominator reduction (deterministic fixed-order sums).
// ---------------------------------------------------------------------------
__global__ void __launch_bounds__(256) k_logits(const float* __restrict__ states,
                                                const float* __restrict__ sa_w,
                                                const float* __restrict__ sa_b, int B) {
    __shared__ __align__(16) float sx[8][L*D];
    __shared__ float sexp[8][L];
    __shared__ float sden[16][17];
    __shared__ bool s_last;
    int tid = threadIdx.x;
    int warp = tid >> 5, lane = tid & 31;
    int borig = blockIdx.x * 8 + warp;
    bool valid = (borig < B);
    int b = valid ? borig : B - 1;

    const float* xs = states + (size_t)b * ROW + 1;
    float xv[4];
#pragma unroll
    for (int i = 0; i < 4; i++) {
        xv[i] = xs[lane + 32*i];
        sx[warp][lane + 32*i] = xv[i];
    }
    __syncwarp();

    // mean: each lane holds 4 values of dim lane&7; xor-reduce over lanes
    float mv = (xv[0] + xv[1]) + (xv[2] + xv[3]);
    mv += __shfl_xor_sync(0xffffffffu, mv, 8);
    mv += __shfl_xor_sync(0xffffffffu, mv, 16);
    mv *= (1.0f / 16.0f);
    float mean[D];
#pragma unroll
    for (int d = 0; d < D; d++) mean[d] = __shfl_sync(0xffffffffu, mv, d);

    // per-lane 4 units: weights in regs, c = ref + bq folded
    float wq[4][D], c[4], sw[4];
#pragma unroll
    for (int j = 0; j < 4; j++) {
        int u = lane + 32*j;
        sw[j] = sa_w[u];
        float r = g_bq[u] + g_br[u];
#pragma unroll
        for (int d = 0; d < D; d++) {
            wq[j][d] = g_WqT[d*U + u];
            r = fmaf(mean[d], g_WrT[d*U + u], r);
        }
        c[j] = r;
    }
    float sab = *sa_b;

    const float4* sxv = (const float4*)sx[warp];
#pragma unroll
    for (int g = 0; g < 2; g++) {
        float v[8];
#pragma unroll
        for (int i = 0; i < 8; i++) {
            int l = g*8 + i;
            float4 x0 = sxv[l*2], x1 = sxv[l*2 + 1];
            float acc = 0.0f;
#pragma unroll
            for (int j = 0; j < 4; j++) {
                float q = dot8v(x0, x1, wq[j], c[j]);
                acc = fmaf(fast_tanh(q), sw[j], acc);
            }
            v[i] = acc;
        }
        red8(v, lane);
        if (lane < 8) {
            int l = g*8 + rev3(lane);
            float e = __expf(v[0] + sab);
            g_elog[(size_t)b*L + l] = e;
            sexp[warp][l] = valid ? e : 0.0f;
        }
    }
    __syncthreads();
    // deterministic fixed-order partial sum over the block's 8 warps
    if (tid < L) {
        float s = 0.0f;
#pragma unroll
        for (int w = 0; w < 8; w++) s += sexp[w][tid];
        g_part[(size_t)blockIdx.x*L + tid] = s;
    }

    // ---- last-block-done: reduce partials -> invden (order-deterministic) ----
    __threadfence();
    if (tid == 0) {
        unsigned int t = atomicAdd(&g_ticket, 1u);
        s_last = (t == gridDim.x - 1);
    }
    __syncthreads();
    if (!s_last) return;

    int nb = gridDim.x;
    int col = tid & 15, slot = tid >> 4;   // 16 threads per column
    float s = 0.0f;
    for (int i = slot; i < nb; i += 16) s += g_part[(size_t)i*L + col];
    sden[col][slot] = s;
    __syncthreads();
    if (tid < 16) {
        float t = 0.0f;
#pragma unroll
        for (int k = 0; k < 16; k++) t += sden[tid][k];
        g_invden[tid] = 1.0f / t;
    }
    if (tid == 16) g_ticket = 0u;   // reset for next graph replay
}

// ---------------------------------------------------------------------------
// Kernel 2: output. One warp per batch element (scalar R6 body: regs ~78).
// ---------------------------------------------------------------------------
__global__ void __launch_bounds__(256) k_out(const float* __restrict__ states,
                                             const float* __restrict__ aq_b,
                                             const float* __restrict__ ar_b,
                                             const float* __restrict__ aa_w,
                                             const float* __restrict__ aa_b,
                                             const int*   __restrict__ pp,
                                             float* __restrict__ out, int B) {
    __shared__ float sx[8][L*D];
    __shared__ float sat[8][L];
    __shared__ float sy[8][P*D];
    __shared__ float ssum[8][P];
    int warp = threadIdx.x >> 5, lane = threadIdx.x & 31;
    int b = blockIdx.x * 8 + warp;
    if (b >= B) return;

    const float* row = states + (size_t)b * ROW;
#pragma unroll
    for (int i = 0; i < 4; i++) sx[warp][lane + 32*i] = row[1 + lane + 32*i];
    if (lane < L) sat[warp][lane] = g_elog[(size_t)b*L + lane] * g_invden[lane];
    int phase = (int)row[0];
    __syncwarp();

    // y_p[d] and s_p
#pragma unroll
    for (int t = 0; t < 2; t++) {
        int idx = lane*2 + t;
        int p = idx >> 3, d = idx & 7;
        int i0 = pp[2*p], i1 = pp[2*p + 1];
        sy[warp][p*D + d] = sat[warp][i0]*sx[warp][i0*D + d] + sat[warp][i1]*sx[warp][i1*D + d];
    }
    if (lane < P) {
        int i0 = pp[2*lane], i1 = pp[2*lane + 1];
        ssum[warp][lane] = sat[warp][i0] + sat[warp][i1];
    }
    __syncwarp();

    float ydp[D];
#pragma unroll
    for (int d = 0; d < D; d++) ydp[d] = sy[warp][phase*D + d];
    float spp = ssum[warp][phase];
    float aab = *aa_b;

    // per-lane 4 units: green + aq_b folded into gb[j]
    float wa[4][D], gb[4], ca[4], aw[4];
#pragma unroll
    for (int j = 0; j < 4; j++) {
        int u = lane + 32*j;
        float g = fmaf(spp, g_car[u], ar_b[u]);
#pragma unroll
        for (int d = 0; d < D; d++) {
            wa[j][d] = g_WaqT[d*U + u];
            g = fmaf(ydp[d], g_WarT[d*U + u], g);
        }
        gb[j] = g + aq_b[u];
        ca[j] = g_caq[u];
        aw[j] = aa_w[u];
    }

    float acc[P];
#pragma unroll
    for (int p = 0; p < P; p++) {
        float yd[D];
#pragma unroll
        for (int d = 0; d < D; d++) yd[d] = sy[warp][p*D + d];
        float sp = ssum[warp][p];
        float a = 0.0f;
#pragma unroll
        for (int j = 0; j < 4; j++) {
            float pq = fmaf(sp, ca[j], gb[j]);
#pragma unroll
            for (int d = 0; d < D; d++) pq = fmaf(yd[d], wa[j][d], pq);
            a = fmaf(fast_tanh(pq), aw[j], a);
        }
        acc[p] = a;
    }
    red8(acc, lane);
    if (lane < 8) out[(size_t)b*P + rev3(lane)] = acc[0] + aab;
}

// ---------------------------------------------------------------------------
extern "C" void kernel_launch(void* const* d_in, const int* in_sizes, int n_in,
                              void* d_out, int out_size) {
    const float* states = (const float*)d_in[0];
    const float* le_w   = (const float*)d_in[1];
    const float* le_b   = (const float*)d_in[2];
    const float* sq_w   = (const float*)d_in[3];
    const float* sq_b   = (const float*)d_in[4];
    const float* sr_w   = (const float*)d_in[5];
    const float* sr_b   = (const float*)d_in[6];
    const float* sa_w   = (const float*)d_in[7];
    const float* sa_b   = (const float*)d_in[8];
    const float* aq_w   = (const float*)d_in[9];
    const float* aq_b   = (const float*)d_in[10];
    const float* ar_w   = (const float*)d_in[11];
    const float* ar_b   = (const float*)d_in[12];
    const float* aa_w   = (const float*)d_in[13];
    const float* aa_b   = (const float*)d_in[14];
    const int*   pp     = (const int*)d_in[15];
    float* out = (float*)d_out;

    int B = in_sizes[0] / ROW;
    if (B > BMAX) B = BMAX;
    int nb = (B + 7) / 8;

    k_compose<<<4, 256>>>(le_w, le_b, sq_w, sq_b, sr_w, sr_b, aq_w, ar_w);
    k_logits<<<nb, 256>>>(states, sa_w, sa_b, B);
    k_out<<<nb, 256>>>(states, aq_b, ar_b, aa_w, aa_b, pp, out, B);
}

// round 9
// speedup vs baseline: 1.2019x; 1.2019x over previous
#include <cuda_runtime.h>

#define BMAX 16384
#define L 16
#define D 8
#define U 128
#define P 8
#define ROW (L*D + 1)
#define NBMAX (BMAX/8)

// ---- composed-weight + softmax scratch (static device arrays; no allocs) ----
__device__ float g_WqT[D*U],  g_bq[U];   // sq_w composed with le_w (transposed [d][u])
__device__ float g_WrT[D*U],  g_br[U];   // sr_w composed
__device__ float g_WaqT[D*U], g_caq[U];  // aq_w composed (caq = aq_w@le_b)
__device__ float g_WarT[D*U], g_car[U];  // ar_w composed
__device__ float g_elog[(size_t)BMAX*L];    // exp(logit)
__device__ float g_part[(size_t)NBMAX*L];   // per-block partial sums of exp
__device__ float g_invden[L];

__device__ __forceinline__ float fast_tanh(float x) {
    float y;
    asm("tanh.approx.f32 %0, %1;" : "=f"(y) : "f"(x));
    return y;
}

// Multi-value butterfly: v[0] on lane r ends with 32-lane sum of index rev3(r&7).
__device__ __forceinline__ void red8(float v[8], int lane) {
#pragma unroll
    for (int m = 1; m <= 4; m <<= 1) {
        int n = (m == 1) ? 8 : (m == 2) ? 4 : 2;
        int h = n >> 1;
        bool up = (lane & m) != 0;
#pragma unroll
        for (int i = 0; i < 4; i++) {
            if (i < h) {
                float send = up ? v[i] : v[i + h];
                float recv = __shfl_xor_sync(0xffffffffu, send, m);
                v[i] = (up ? v[i + h] : v[i]) + recv;
            }
        }
    }
    v[0] += __shfl_xor_sync(0xffffffffu, v[0], 8);
    v[0] += __shfl_xor_sync(0xffffffffu, v[0], 16);
}

__device__ __forceinline__ int rev3(int r) {
    return ((r & 1) << 2) | (r & 2) | ((r & 4) >> 2);
}

// dot of (a0|a1) with 8 scalar weights
__device__ __forceinline__ float dot8v(float4 a0, float4 a1, const float* w, float init) {
    float q = init;
    q = fmaf(a0.x, w[0], q); q = fmaf(a0.y, w[1], q);
    q = fmaf(a0.z, w[2], q); q = fmaf(a0.w, w[3], q);
    q = fmaf(a1.x, w[4], q); q = fmaf(a1.y, w[5], q);
    q = fmaf(a1.z, w[6], q); q = fmaf(a1.w, w[7], q);
    return q;
}

// ---------------------------------------------------------------------------
// Kernel 0: fold le_w/le_b through the four 128x128 linears.
// 4 blocks x 1024 threads: u = tid&127, slice = tid>>7 (8 slices x 16 k).
// Each thread: 4 independent LDG.128 (MLP=4), fixed-order smem reduction.
// ---------------------------------------------------------------------------
__global__ void __launch_bounds__(1024) k_compose(
                          const float* __restrict__ le_w, const float* __restrict__ le_b,
                          const float* __restrict__ sq_w, const float* __restrict__ sq_b,
                          const float* __restrict__ sr_w, const float* __restrict__ sr_b,
                          const float* __restrict__ aq_w,
                          const float* __restrict__ ar_w) {
    __shared__ float sle[U*D], sleb[U];
    __shared__ float spart[8][U][D + 1];   // [slice][u][d or bias]
    int tid = threadIdx.x;
    int u = tid & 127, slice = tid >> 7;
    if (slice == 0) {
#pragma unroll
        for (int d = 0; d < D; d++) sle[u*D + d] = le_w[u*D + d];
        sleb[u] = le_b[u];
    }
    __syncthreads();

    int m = blockIdx.x;
    const float* W = (m == 0) ? sq_w : (m == 1) ? sr_w : (m == 2) ? aq_w : ar_w;

    int k0 = slice * 16;
    // 4 independent vector loads of this thread's 16 W values
    const float4* Wv = (const float4*)(W + u*U + k0);
    float4 w4[4];
#pragma unroll
    for (int i = 0; i < 4; i++) w4[i] = Wv[i];

    float acc[D];
#pragma unroll
    for (int d = 0; d < D; d++) acc[d] = 0.0f;
    float ab = 0.0f;
    const float* wf = (const float*)w4;
#pragma unroll
    for (int kk = 0; kk < 16; kk++) {
        float w = wf[kk];
        int k = k0 + kk;
        ab = fmaf(w, sleb[k], ab);
#pragma unroll
        for (int d = 0; d < D; d++) acc[d] = fmaf(w, sle[k*D + d], acc[d]);
    }
#pragma unroll
    for (int d = 0; d < D; d++) spart[slice][u][d] = acc[d];
    spart[slice][u][D] = ab;
    __syncthreads();

    if (slice == 0) {
        float tot[D + 1];
#pragma unroll
        for (int d = 0; d <= D; d++) {
            float s = 0.0f;
#pragma unroll
            for (int sl = 0; sl < 8; sl++) s += spart[sl][u][d];   // fixed order
            tot[d] = s;
        }
        float* WT = (m == 0) ? g_WqT : (m == 1) ? g_WrT : (m == 2) ? g_WaqT : g_WarT;
#pragma unroll
        for (int d = 0; d < D; d++) WT[d*U + u] = tot[d];
        float ab2 = tot[D];
        if      (m == 0) g_bq[u]  = ab2 + sq_b[u];
        else if (m == 1) g_br[u]  = ab2 + sr_b[u];
        else if (m == 2) g_caq[u] = ab2;
        else             g_car[u] = ab2;
    }
}

// ---------------------------------------------------------------------------
// Kernel 1: attention logits -> exp(logit) + per-block partials.
// One warp per batch element, 8 warps/block; float4 LDS in the main loop.
// ---------------------------------------------------------------------------
__global__ void __launch_bounds__(256) k_logits(const float* __restrict__ states,
                                                const float* __restrict__ sa_w,
                                                const float* __restrict__ sa_b, int B) {
    __shared__ __align__(16) float sx[8][L*D];
    __shared__ float sexp[8][L];
    int tid = threadIdx.x;
    int warp = tid >> 5, lane = tid & 31;
    int borig = blockIdx.x * 8 + warp;
    bool valid = (borig < B);
    int b = valid ? borig : B - 1;

    const float* xs = states + (size_t)b * ROW + 1;
    float xv[4];
#pragma unroll
    for (int i = 0; i < 4; i++) {
        xv[i] = xs[lane + 32*i];
        sx[warp][lane + 32*i] = xv[i];
    }
    __syncwarp();

    // mean: each lane holds 4 values of dim lane&7; xor-reduce over lanes
    float mv = (xv[0] + xv[1]) + (xv[2] + xv[3]);
    mv += __shfl_xor_sync(0xffffffffu, mv, 8);
    mv += __shfl_xor_sync(0xffffffffu, mv, 16);
    mv *= (1.0f / 16.0f);
    float mean[D];
#pragma unroll
    for (int d = 0; d < D; d++) mean[d] = __shfl_sync(0xffffffffu, mv, d);

    // per-lane 4 units: weights in regs, c = ref + bq folded
    float wq[4][D], c[4], sw[4];
#pragma unroll
    for (int j = 0; j < 4; j++) {
        int u = lane + 32*j;
        sw[j] = sa_w[u];
        float r = g_bq[u] + g_br[u];
#pragma unroll
        for (int d = 0; d < D; d++) {
            wq[j][d] = g_WqT[d*U + u];
            r = fmaf(mean[d], g_WrT[d*U + u], r);
        }
        c[j] = r;
    }
    float sab = *sa_b;

    const float4* sxv = (const float4*)sx[warp];
#pragma unroll
    for (int g = 0; g < 2; g++) {
        float v[8];
#pragma unroll
        for (int i = 0; i < 8; i++) {
            int l = g*8 + i;
            float4 x0 = sxv[l*2], x1 = sxv[l*2 + 1];
            float acc = 0.0f;
#pragma unroll
            for (int j = 0; j < 4; j++) {
                float q = dot8v(x0, x1, wq[j], c[j]);
                acc = fmaf(fast_tanh(q), sw[j], acc);
            }
            v[i] = acc;
        }
        red8(v, lane);
        if (lane < 8) {
            int l = g*8 + rev3(lane);
            float e = __expf(v[0] + sab);
            g_elog[(size_t)b*L + l] = e;
            sexp[warp][l] = valid ? e : 0.0f;
        }
    }
    __syncthreads();
    // deterministic fixed-order partial sum over the block's 8 warps
    if (tid < L) {
        float s = 0.0f;
#pragma unroll
        for (int w = 0; w < 8; w++) s += sexp[w][tid];
        g_part[(size_t)blockIdx.x*L + tid] = s;
    }
}

// ---------------------------------------------------------------------------
// Kernel 2: reduce per-block partials -> 1/denominator per column.
// ---------------------------------------------------------------------------
__global__ void k_den(int nb) {
    int l = blockIdx.x;
    int tid = threadIdx.x;
    float s = 0.0f;
    for (int i = tid; i < nb; i += 256) s += g_part[(size_t)i*L + l];
    __shared__ float red[256];
    red[tid] = s;
    __syncthreads();
    for (int o = 128; o > 0; o >>= 1) {
        if (tid < o) red[tid] += red[tid + o];
        __syncthreads();
    }
    if (tid == 0) g_invden[l] = 1.0f / red[0];
}

// ---------------------------------------------------------------------------
// Kernel 3: output. One warp per batch element (scalar R6 body: regs ~78).
// ---------------------------------------------------------------------------
__global__ void __launch_bounds__(256) k_out(const float* __restrict__ states,
                                             const float* __restrict__ aq_b,
                                             const float* __restrict__ ar_b,
                                             const float* __restrict__ aa_w,
                                             const float* __restrict__ aa_b,
                                             const int*   __restrict__ pp,
                                             float* __restrict__ out, int B) {
    __shared__ float sx[8][L*D];
    __shared__ float sat[8][L];
    __shared__ float sy[8][P*D];
    __shared__ float ssum[8][P];
    int warp = threadIdx.x >> 5, lane = threadIdx.x & 31;
    int b = blockIdx.x * 8 + warp;
    if (b >= B) return;

    const float* row = states + (size_t)b * ROW;
#pragma unroll
    for (int i = 0; i < 4; i++) sx[warp][lane + 32*i] = row[1 + lane + 32*i];
    if (lane < L) sat[warp][lane] = g_elog[(size_t)b*L + lane] * g_invden[lane];
    int phase = (int)row[0];
    __syncwarp();

    // y_p[d] and s_p
#pragma unroll
    for (int t = 0; t < 2; t++) {
        int idx = lane*2 + t;
        int p = idx >> 3, d = idx & 7;
        int i0 = pp[2*p], i1 = pp[2*p + 1];
        sy[warp][p*D + d] = sat[warp][i0]*sx[warp][i0*D + d] + sat[warp][i1]*sx[warp][i1*D + d];
    }
    if (lane < P) {
        int i0 = pp[2*lane], i1 = pp[2*lane + 1];
        ssum[warp][lane] = sat[warp][i0] + sat[warp][i1];
    }
    __syncwarp();

    float ydp[D];
#pragma unroll
    for (int d = 0; d < D; d++) ydp[d] = sy[warp][phase*D + d];
    float spp = ssum[warp][phase];
    float aab = *aa_b;

    // per-lane 4 units: green + aq_b folded into gb[j]
    float wa[4][D], gb[4], ca[4], aw[4];
#pragma unroll
    for (int j = 0; j < 4; j++) {
        int u = lane + 32*j;
        float g = fmaf(spp, g_car[u], ar_b[u]);
#pragma unroll
        for (int d = 0; d < D; d++) {
            wa[j][d] = g_WaqT[d*U + u];
            g = fmaf(ydp[d], g_WarT[d*U + u], g);
        }
        gb[j] = g + aq_b[u];
        ca[j] = g_caq[u];
        aw[j] = aa_w[u];
    }

    float acc[P];
#pragma unroll
    for (int p = 0; p < P; p++) {
        float yd[D];
#pragma unroll
        for (int d = 0; d < D; d++) yd[d] = sy[warp][p*D + d];
        float sp = ssum[warp][p];
        float a = 0.0f;
#pragma unroll
        for (int j = 0; j < 4; j++) {
            float pq = fmaf(sp, ca[j], gb[j]);
#pragma unroll
            for (int d = 0; d < D; d++) pq = fmaf(yd[d], wa[j][d], pq);
            a = fmaf(fast_tanh(pq), aw[j], a);
        }
        acc[p] = a;
    }
    red8(acc, lane);
    if (lane < 8) out[(size_t)b*P + rev3(lane)] = acc[0] + aab;
}

// ---------------------------------------------------------------------------
extern "C" void kernel_launch(void* const* d_in, const int* in_sizes, int n_in,
                              void* d_out, int out_size) {
    const float* states = (const float*)d_in[0];
    const float* le_w   = (const float*)d_in[1];
    const float* le_b   = (const float*)d_in[2];
    const float* sq_w   = (const float*)d_in[3];
    const float* sq_b   = (const float*)d_in[4];
    const float* sr_w   = (const float*)d_in[5];
    const float* sr_b   = (const float*)d_in[6];
    const float* sa_w   = (const float*)d_in[7];
    const float* sa_b   = (const float*)d_in[8];
    const float* aq_w   = (const float*)d_in[9];
    const float* aq_b   = (const float*)d_in[10];
    const float* ar_w   = (const float*)d_in[11];
    const float* ar_b   = (const float*)d_in[12];
    const float* aa_w   = (const float*)d_in[13];
    const float* aa_b   = (const float*)d_in[14];
    const int*   pp     = (const int*)d_in[15];
    float* out = (float*)d_out;

    int B = in_sizes[0] / ROW;
    if (B > BMAX) B = BMAX;
    int nb = (B + 7) / 8;

    k_compose<<<4, 1024>>>(le_w, le_b, sq_w, sq_b, sr_w, sr_b, aq_w, ar_w);
    k_logits<<<nb, 256>>>(states, sa_w, sa_b, B);
    k_den<<<L, 256>>>(nb);
    k_out<<<nb, 256>>>(states, aq_b, ar_b, aa_w, aa_b, pp, out, B);
}